// round 2
// baseline (speedup 1.0000x reference)
#include <cuda_runtime.h>

// QLSTM collapsed analytically:
//   quantum_gate(comb, p)[:, k] = prod_{j<=k} cos(p_j) * cos(comb_j)
// Only k < H=4 used and comb[0:4] = x  => gates depend only on x_t.
// Per (b,k):  c_t = f_t*c_{t-1} + i_t*g_t ;  h_t = o_t*tanh(c_t)
//   arg = A_k * P_k(t,b), |A|<=1, |P|<=1  => gate args in [-1,1].
// Sigmoids (f,i,o) via deg-9 odd poly on u=arg/2 in [-0.5,0.5] (err ~2e-6),
// tanh (g, final) via exp (2 MUFU) for accuracy over |c|<=2.1.
// Parallel scan over T: warp = batch element, lane = (chunk 0..7, k 0..3).

#define T_STEPS 128
#define BATCH   4096
#define HID     4
#define CHUNK   16
#define NCHUNK  8
#define FULLMASK 0xffffffffu

__device__ __forceinline__ float fast_tanh(float z) {
    // 1 - 2/(e^{2z}+1); accurate to ~1ulp of MUFU chain, handles saturation
    return 1.0f - __fdividef(2.0f, __expf(2.0f * z) + 1.0f);
}

// sigmoid(2u) for |u| <= 0.5 : 0.5 + u * q(u^2), q = halved tanh Taylor deg-9
__device__ __forceinline__ float sig_poly(float u) {
    float w = u * u;
    float q = fmaf(w, fmaf(w, fmaf(w, fmaf(w, 0.010934744f,
                                              -0.026984127f),
                                       0.066666667f),
                               -0.166666667f),
                       0.5f);
    return fmaf(u, q, 0.5f);
}

__global__ void __launch_bounds__(128, 6) qlstm_kernel(
    const float* __restrict__ inp,   // [T, B, 4]
    const float* __restrict__ prm_f, // [8]
    const float* __restrict__ prm_i,
    const float* __restrict__ prm_g,
    const float* __restrict__ prm_o,
    float* __restrict__ out)         // [T*B*H + B*H + B*H]
{
    const int warp_id = (blockIdx.x * blockDim.x + threadIdx.x) >> 5;
    const int b     = warp_id;         // grid gives exactly BATCH warps
    const int lane  = threadIdx.x & 31;
    const int k     = lane & 3;        // hidden index 0..3
    const int chunk = lane >> 2;       // time chunk 0..7

    // per-k parameter prefix products: A_k = prod_{j<=k} cos(p_j)
    float AF = 1.0f, AI = 1.0f, AG = 1.0f, AO = 1.0f;
#pragma unroll
    for (int j = 0; j < HID; ++j) {
        if (j <= k) {
            AF *= __cosf(prm_f[j]);
            AI *= __cosf(prm_i[j]);
            AG *= __cosf(prm_g[j]);
            AO *= __cosf(prm_o[j]);
        }
    }
    // prescale sigmoid params by 0.5 (poly takes u = arg/2)
    AF *= 0.5f; AI *= 0.5f; AO *= 0.5f;

    // phase 1: chunk-local gates + affine scan state (c0, prod f)
    float o_arr[CHUNK];
    float c0_arr[CHUNK];
    float pf_arr[CHUNK];

    float c_loc = 0.0f;
    float pf    = 1.0f;

    const float4* __restrict__ xin = (const float4*)inp;
    const int t0 = chunk * CHUNK;

#pragma unroll
    for (int it = 0; it < CHUNK; ++it) {
        const int t = t0 + it;
        float4 x4 = xin[t * BATCH + b];
        float xk = (k == 0) ? x4.x : (k == 1) ? x4.y : (k == 2) ? x4.z : x4.w;

        // segmented (groups of 4) inclusive prefix product of cos(x_j)
        float P = __cosf(xk);
        float s1 = __shfl_up_sync(FULLMASK, P, 1);
        if (k >= 1) P *= s1;
        float s2 = __shfl_up_sync(FULLMASK, P, 2);
        if (k >= 2) P *= s2;

        float f = sig_poly(AF * P);
        float i = sig_poly(AI * P);
        float g = fast_tanh(AG * P);
        float o = sig_poly(AO * P);

        c_loc = fmaf(f, c_loc, i * g);
        pf    = pf * f;

        o_arr[it]  = o;
        c0_arr[it] = c_loc;
        pf_arr[it] = pf;
    }

    // phase 2: warp scan over 8 chunks (stride-4 lanes share k)
    float F = pf, C = c_loc;
#pragma unroll
    for (int off = 4; off <= 16; off <<= 1) {
        float Fo = __shfl_up_sync(FULLMASK, F, off);
        float Co = __shfl_up_sync(FULLMASK, C, off);
        if (lane >= off) {
            C = fmaf(F, Co, C);
            F = F * Fo;
        }
    }
    float cin = __shfl_up_sync(FULLMASK, C, 4);
    if (chunk == 0) cin = 0.0f;

    // phase 3: reconstruct c_t, emit h_t
    const int bk = b * HID + k;
#pragma unroll
    for (int it = 0; it < CHUNK; ++it) {
        const int t = t0 + it;
        float ct = fmaf(pf_arr[it], cin, c0_arr[it]);
        float h  = o_arr[it] * fast_tanh(ct);
        out[t * (BATCH * HID) + bk] = h;
        if (chunk == NCHUNK - 1 && it == CHUNK - 1) {
            out[T_STEPS * BATCH * HID + bk] = h;                     // hx
            out[T_STEPS * BATCH * HID + BATCH * HID + bk] = ct;      // cx
        }
    }
}

extern "C" void kernel_launch(void* const* d_in, const int* in_sizes, int n_in,
                              void* d_out, int out_size) {
    (void)in_sizes; (void)n_in; (void)out_size;
    const float* inp   = (const float*)d_in[0];
    const float* prm_f = (const float*)d_in[1];
    const float* prm_i = (const float*)d_in[2];
    const float* prm_g = (const float*)d_in[3];
    const float* prm_o = (const float*)d_in[4];
    float* out = (float*)d_out;

    // one warp per batch element, 4 warps per block -> finer wave granularity
    qlstm_kernel<<<BATCH / 4, 128>>>(inp, prm_f, prm_i, prm_g, prm_o, out);
}

// round 3
// speedup vs baseline: 1.2557x; 1.2557x over previous
#include <cuda_runtime.h>

// QLSTM collapsed analytically:
//   quantum_gate(comb, p)[:, k] = prod_{j<=k} cos(p_j) * cos(comb_j)
// Only k < H=4 used and comb[0:4] = x  => gates depend only on x_t.
// Per (b,k):  c_t = f_t*c_{t-1} + i_t*g_t ;  h_t = o_t*tanh(c_t)
// Gate args = A_k * P_k(t,b) with |A|<=1, |P|<=1  => args in [-1,1], |c|<=1.8.
//
// Two-pass, array-free (no register spills):
//   pass 1: chunk-local (prod f, c from 0), cache P[16] in regs
//   warp scan over 8 chunks -> cin
//   pass 2: true sequential recurrence from cin, emit h
// Warp = batch element; lane = (chunk 0..7) x (k 0..3); chunk = 16 steps.

#define T_STEPS 128
#define BATCH   4096
#define HID     4
#define CHUNK   16
#define NCHUNK  8
#define FULLMASK 0xffffffffu

// sigmoid(2u) for |u| <= 0.5 : 0.5 + u*q(u^2); halved tanh Taylor deg-9, err ~2e-6
__device__ __forceinline__ float sig_poly(float u) {
    float w = u * u;
    float q = fmaf(w, fmaf(w, fmaf(w, fmaf(w, 0.010934744f,
                                              -0.026984127f),
                                       0.066666667f),
                               -0.166666667f),
                       0.5f);
    return fmaf(u, q, 0.5f);
}

// tanh Pade(5,4): z(945+105z^2+z^4)/(945+420z^2+15z^4); |z|<=1, err ~4e-8
__device__ __forceinline__ float tanh_p54(float z) {
    float w = z * z;
    float n = z * fmaf(w, fmaf(w, 1.0f, 105.0f), 945.0f);
    float d =     fmaf(w, fmaf(w, 15.0f, 420.0f), 945.0f);
    return __fdividef(n, d);
}

// tanh Pade(7,6): z(10395+1260z^2+21z^4)/(10395+4725z^2+210z^4+z^6); |z|<=2.5, err ~1e-6
__device__ __forceinline__ float tanh_p76(float z) {
    float w = z * z;
    float n = z * fmaf(w, fmaf(w, 21.0f, 1260.0f), 10395.0f);
    float d =     fmaf(w, fmaf(w, fmaf(w, 1.0f, 210.0f), 4725.0f), 10395.0f);
    return __fdividef(n, d);
}

__global__ void __launch_bounds__(256) qlstm_kernel(
    const float* __restrict__ inp,   // [T, B, 4]
    const float* __restrict__ prm_f, // [8]
    const float* __restrict__ prm_i,
    const float* __restrict__ prm_g,
    const float* __restrict__ prm_o,
    float* __restrict__ out)         // [T*B*H + B*H + B*H]
{
    const int b     = (blockIdx.x * blockDim.x + threadIdx.x) >> 5;
    const int lane  = threadIdx.x & 31;
    const int k     = lane & 3;        // hidden index 0..3
    const int chunk = lane >> 2;       // time chunk 0..7

    // per-k parameter prefix products: A_k = prod_{j<=k} cos(p_j)
    float AF = 1.0f, AI = 1.0f, AG = 1.0f, AO = 1.0f;
#pragma unroll
    for (int j = 0; j < HID; ++j) {
        if (j <= k) {
            AF *= __cosf(prm_f[j]);
            AI *= __cosf(prm_i[j]);
            AG *= __cosf(prm_g[j]);
            AO *= __cosf(prm_o[j]);
        }
    }
    // prescale sigmoid params by 0.5 (sig_poly takes u = arg/2)
    const float AFh = AF * 0.5f, AIh = AI * 0.5f, AOh = AO * 0.5f;

    const float4* __restrict__ xin = (const float4*)inp;
    const int t0 = chunk * CHUNK;

    // ---- pass 1: cache P, accumulate chunk affine map (pf, c_loc) ----
    float Pc[CHUNK];                 // prefix cos products (static-indexed -> regs)
    float c_loc = 0.0f;
    float pf    = 1.0f;

#pragma unroll
    for (int it = 0; it < CHUNK; ++it) {
        float4 x4 = xin[(t0 + it) * BATCH + b];
        float xk = (k == 0) ? x4.x : (k == 1) ? x4.y : (k == 2) ? x4.z : x4.w;

        // segmented (groups of 4) inclusive prefix product of cos(x_j)
        float P = __cosf(xk);
        float s1 = __shfl_up_sync(FULLMASK, P, 1);
        if (k >= 1) P *= s1;
        float s2 = __shfl_up_sync(FULLMASK, P, 2);
        if (k >= 2) P *= s2;
        Pc[it] = P;

        float f = sig_poly(AFh * P);
        float i = sig_poly(AIh * P);
        float g = tanh_p54(AG  * P);

        c_loc = fmaf(f, c_loc, i * g);
        pf    = pf * f;
    }

    // ---- scan over 8 chunks (stride-4 lanes share k): c_out = C + F*c_in ----
    float F = pf, C = c_loc;
#pragma unroll
    for (int off = 4; off <= 16; off <<= 1) {
        float Fo = __shfl_up_sync(FULLMASK, F, off);
        float Co = __shfl_up_sync(FULLMASK, C, off);
        if (lane >= off) {
            C = fmaf(F, Co, C);
            F = F * Fo;
        }
    }
    float cin = __shfl_up_sync(FULLMASK, C, 4);
    if (chunk == 0) cin = 0.0f;

    // ---- pass 2: true recurrence from cin, emit h ----
    const int bk = b * HID + k;
    float c = cin;
#pragma unroll
    for (int it = 0; it < CHUNK; ++it) {
        float P = Pc[it];
        float f = sig_poly(AFh * P);
        float i = sig_poly(AIh * P);
        float g = tanh_p54(AG  * P);
        float o = sig_poly(AOh * P);

        c = fmaf(f, c, i * g);
        float h = o * tanh_p76(c);

        out[(t0 + it) * (BATCH * HID) + bk] = h;
        if (chunk == NCHUNK - 1 && it == CHUNK - 1) {
            out[T_STEPS * BATCH * HID + bk] = h;                 // hx
            out[T_STEPS * BATCH * HID + BATCH * HID + bk] = c;   // cx
        }
    }
}

extern "C" void kernel_launch(void* const* d_in, const int* in_sizes, int n_in,
                              void* d_out, int out_size) {
    (void)in_sizes; (void)n_in; (void)out_size;
    const float* inp   = (const float*)d_in[0];
    const float* prm_f = (const float*)d_in[1];
    const float* prm_i = (const float*)d_in[2];
    const float* prm_g = (const float*)d_in[3];
    const float* prm_o = (const float*)d_in[4];
    float* out = (float*)d_out;

    qlstm_kernel<<<BATCH / 8, 256>>>(inp, prm_f, prm_i, prm_g, prm_o, out);
}

// round 4
// speedup vs baseline: 1.2949x; 1.0313x over previous
#include <cuda_runtime.h>

// QLSTM collapsed analytically:
//   quantum_gate(comb, p)[:, k] = prod_{j<=k} cos(p_j) * cos(comb_j)
// Only k < H=4 used; comb[0:4] = x  => gates depend only on x_t.
// Per (b,k): c_t = f*c + i*g ; h = o*tanh(c); args in [-1,1], |c| <= 2.1.
//
// Mapping: ONE THREAD OWNS ALL 4 k-CHAINS for one (b, time-chunk).
//   P0..P3 = running cos products of one float4 -> no shuffles.
//   warp = 4 consecutive b x 8 chunks of 16 steps; scan via 3 shuffle rounds.
//   loads/stores: 64B contiguous per 4-lane group, h stored as float4.
// Two passes (aggregate scan, then true recurrence) -> no per-step arrays.

#define T_STEPS 128
#define BATCH   4096
#define CHUNK   16
#define NCHUNK  8
#define FULLMASK 0xffffffffu

// sigmoid(2u), |u|<=0.5 : 0.5 + u*q(u^2); tanh Taylor deg-9 halved, err ~2e-6
__device__ __forceinline__ float sig_poly(float u) {
    float w = u * u;
    float q = fmaf(w, fmaf(w, fmaf(w, fmaf(w, 0.010934744f,
                                              -0.026984127f),
                                       0.066666667f),
                               -0.166666667f),
                       0.5f);
    return fmaf(u, q, 0.5f);
}
// tanh Pade(5,4); |z|<=1, err ~4e-8
__device__ __forceinline__ float tanh_p54(float z) {
    float w = z * z;
    float n = z * fmaf(w, fmaf(w, 1.0f, 105.0f), 945.0f);
    float d =     fmaf(w, fmaf(w, 15.0f, 420.0f), 945.0f);
    return __fdividef(n, d);
}
// tanh Pade(7,6); |z|<=2.5, err ~1e-6
__device__ __forceinline__ float tanh_p76(float z) {
    float w = z * z;
    float n = z * fmaf(w, fmaf(w, 21.0f, 1260.0f), 10395.0f);
    float d =     fmaf(w, fmaf(w, fmaf(w, 1.0f, 210.0f), 4725.0f), 10395.0f);
    return __fdividef(n, d);
}

__global__ void __launch_bounds__(128, 6) qlstm_kernel(
    const float* __restrict__ inp,   // [T, B, 4]
    const float* __restrict__ prm_f, // [8]
    const float* __restrict__ prm_i,
    const float* __restrict__ prm_g,
    const float* __restrict__ prm_o,
    float* __restrict__ out)         // [T*B*4 + B*4 + B*4]
{
    const int gtid    = blockIdx.x * blockDim.x + threadIdx.x;
    const int warp_id = gtid >> 5;
    const int lane    = threadIdx.x & 31;
    const int bsub    = lane & 3;
    const int chunk   = lane >> 2;
    const int b       = warp_id * 4 + bsub;

    // per-k parameter prefix products (uniform across threads)
    float AFh[4], AIh[4], AG[4], AOh[4];
    {
        float pf_ = 1.0f, pi_ = 1.0f, pg_ = 1.0f, po_ = 1.0f;
#pragma unroll
        for (int j = 0; j < 4; ++j) {
            pf_ *= __cosf(prm_f[j]);
            pi_ *= __cosf(prm_i[j]);
            pg_ *= __cosf(prm_g[j]);
            po_ *= __cosf(prm_o[j]);
            AFh[j] = 0.5f * pf_;   // sigmoid polys take arg/2
            AIh[j] = 0.5f * pi_;
            AG[j]  = pg_;
            AOh[j] = 0.5f * po_;
        }
    }

    const float4* __restrict__ xin = (const float4*)inp;
    const int t0 = chunk * CHUNK;

    // ---- pass 1: chunk-local affine aggregates per k ----
    float cl0 = 0.f, cl1 = 0.f, cl2 = 0.f, cl3 = 0.f;
    float pf0 = 1.f, pf1 = 1.f, pf2 = 1.f, pf3 = 1.f;

#pragma unroll
    for (int it = 0; it < CHUNK; ++it) {
        float4 x = xin[(t0 + it) * BATCH + b];
        float P0 = __cosf(x.x);
        float P1 = P0 * __cosf(x.y);
        float P2 = P1 * __cosf(x.z);
        float P3 = P2 * __cosf(x.w);

        float f, i, g;
        f = sig_poly(AFh[0] * P0); i = sig_poly(AIh[0] * P0); g = tanh_p54(AG[0] * P0);
        cl0 = fmaf(f, cl0, i * g); pf0 *= f;
        f = sig_poly(AFh[1] * P1); i = sig_poly(AIh[1] * P1); g = tanh_p54(AG[1] * P1);
        cl1 = fmaf(f, cl1, i * g); pf1 *= f;
        f = sig_poly(AFh[2] * P2); i = sig_poly(AIh[2] * P2); g = tanh_p54(AG[2] * P2);
        cl2 = fmaf(f, cl2, i * g); pf2 *= f;
        f = sig_poly(AFh[3] * P3); i = sig_poly(AIh[3] * P3); g = tanh_p54(AG[3] * P3);
        cl3 = fmaf(f, cl3, i * g); pf3 *= f;
    }

    // ---- scan over 8 chunks (lanes stride 4 share b): c_out = C + F*c_in ----
    float F0 = pf0, C0 = cl0, F1 = pf1, C1 = cl1;
    float F2 = pf2, C2 = cl2, F3 = pf3, C3 = cl3;
#pragma unroll
    for (int off = 4; off <= 16; off <<= 1) {
        float Fo0 = __shfl_up_sync(FULLMASK, F0, off), Co0 = __shfl_up_sync(FULLMASK, C0, off);
        float Fo1 = __shfl_up_sync(FULLMASK, F1, off), Co1 = __shfl_up_sync(FULLMASK, C1, off);
        float Fo2 = __shfl_up_sync(FULLMASK, F2, off), Co2 = __shfl_up_sync(FULLMASK, C2, off);
        float Fo3 = __shfl_up_sync(FULLMASK, F3, off), Co3 = __shfl_up_sync(FULLMASK, C3, off);
        if (lane >= off) {
            C0 = fmaf(F0, Co0, C0); F0 *= Fo0;
            C1 = fmaf(F1, Co1, C1); F1 *= Fo1;
            C2 = fmaf(F2, Co2, C2); F2 *= Fo2;
            C3 = fmaf(F3, Co3, C3); F3 *= Fo3;
        }
    }
    float c0 = __shfl_up_sync(FULLMASK, C0, 4);
    float c1 = __shfl_up_sync(FULLMASK, C1, 4);
    float c2 = __shfl_up_sync(FULLMASK, C2, 4);
    float c3 = __shfl_up_sync(FULLMASK, C3, 4);
    if (chunk == 0) { c0 = 0.f; c1 = 0.f; c2 = 0.f; c3 = 0.f; }

    // ---- pass 2: true recurrence from cin, emit h as float4 ----
    float4* __restrict__ out4 = (float4*)out;
    float h0 = 0.f, h1 = 0.f, h2 = 0.f, h3 = 0.f;

#pragma unroll
    for (int it = 0; it < CHUNK; ++it) {
        float4 x = xin[(t0 + it) * BATCH + b];
        float P0 = __cosf(x.x);
        float P1 = P0 * __cosf(x.y);
        float P2 = P1 * __cosf(x.z);
        float P3 = P2 * __cosf(x.w);

        float f, i, g, o;
        f = sig_poly(AFh[0] * P0); i = sig_poly(AIh[0] * P0);
        g = tanh_p54(AG[0] * P0); o = sig_poly(AOh[0] * P0);
        c0 = fmaf(f, c0, i * g);   h0 = o * tanh_p76(c0);

        f = sig_poly(AFh[1] * P1); i = sig_poly(AIh[1] * P1);
        g = tanh_p54(AG[1] * P1); o = sig_poly(AOh[1] * P1);
        c1 = fmaf(f, c1, i * g);   h1 = o * tanh_p76(c1);

        f = sig_poly(AFh[2] * P2); i = sig_poly(AIh[2] * P2);
        g = tanh_p54(AG[2] * P2); o = sig_poly(AOh[2] * P2);
        c2 = fmaf(f, c2, i * g);   h2 = o * tanh_p76(c2);

        f = sig_poly(AFh[3] * P3); i = sig_poly(AIh[3] * P3);
        g = tanh_p54(AG[3] * P3); o = sig_poly(AOh[3] * P3);
        c3 = fmaf(f, c3, i * g);   h3 = o * tanh_p76(c3);

        out4[(t0 + it) * BATCH + b] = make_float4(h0, h1, h2, h3);
    }

    if (chunk == NCHUNK - 1) {
        out4[T_STEPS * BATCH + b]         = make_float4(h0, h1, h2, h3); // hx
        out4[T_STEPS * BATCH + BATCH + b] = make_float4(c0, c1, c2, c3); // cx
    }
}

extern "C" void kernel_launch(void* const* d_in, const int* in_sizes, int n_in,
                              void* d_out, int out_size) {
    (void)in_sizes; (void)n_in; (void)out_size;
    const float* inp   = (const float*)d_in[0];
    const float* prm_f = (const float*)d_in[1];
    const float* prm_i = (const float*)d_in[2];
    const float* prm_g = (const float*)d_in[3];
    const float* prm_o = (const float*)d_in[4];
    float* out = (float*)d_out;

    // BATCH/4 warps * 32 = 32768 threads; 128-thread blocks -> 256 blocks
    qlstm_kernel<<<256, 128>>>(inp, prm_f, prm_i, prm_g, prm_o, out);
}

// round 5
// speedup vs baseline: 1.9791x; 1.5284x over previous
#include <cuda_runtime.h>

// QLSTM collapsed analytically:
//   quantum_gate(comb, p)[:, k] = prod_{j<=k} cos(p_j) * cos(comb_j)
// Only k < H=4 used; comb[0:4] = x  => gates depend only on x_t.
// Per (b,k): c_t = f*c + i*g ; h = o*tanh(c); gate args in [-1,1], |c| <= 2.1.
//
// Mapping: thread owns all 4 k-chains for (b, 8-step time chunk).
//   lane = (chunk 0..15) * 2 + (bsub 0..1); warp covers 2 batch x 16 chunks.
//   Pass 1: chunk-local affine aggregates, caching (f, i*g) in registers.
//   Warp scan (4 rounds) composes chunk maps -> cin per chunk.
//   Pass 2: exact recurrence using cached (f, i*g); reload x only for o-gate.

#define T_STEPS 128
#define BATCH   4096
#define CHUNK   8
#define NCHUNK  16
#define FULLMASK 0xffffffffu

// sigmoid(2u), |u|<=0.5 : 0.5 + u*q(u^2); tanh Taylor deg-9 halved, err ~2e-6
__device__ __forceinline__ float sig_poly(float u) {
    float w = u * u;
    float q = fmaf(w, fmaf(w, fmaf(w, fmaf(w, 0.010934744f,
                                              -0.026984127f),
                                       0.066666667f),
                               -0.166666667f),
                       0.5f);
    return fmaf(u, q, 0.5f);
}
// tanh Pade(5,4); |z|<=1, err ~4e-8
__device__ __forceinline__ float tanh_p54(float z) {
    float w = z * z;
    float n = z * fmaf(w, fmaf(w, 1.0f, 105.0f), 945.0f);
    float d =     fmaf(w, fmaf(w, 15.0f, 420.0f), 945.0f);
    return __fdividef(n, d);
}
// tanh Pade(7,6); |z|<=2.5, err ~1e-6
__device__ __forceinline__ float tanh_p76(float z) {
    float w = z * z;
    float n = z * fmaf(w, fmaf(w, 21.0f, 1260.0f), 10395.0f);
    float d =     fmaf(w, fmaf(w, fmaf(w, 1.0f, 210.0f), 4725.0f), 10395.0f);
    return __fdividef(n, d);
}

__global__ void __launch_bounds__(128, 4) qlstm_kernel(
    const float* __restrict__ inp,   // [T, B, 4]
    const float* __restrict__ prm_f, // [8]
    const float* __restrict__ prm_i,
    const float* __restrict__ prm_g,
    const float* __restrict__ prm_o,
    float* __restrict__ out)         // [T*B*4 + B*4 + B*4]
{
    const int gtid    = blockIdx.x * blockDim.x + threadIdx.x;
    const int warp_id = gtid >> 5;
    const int lane    = threadIdx.x & 31;
    const int bsub    = lane & 1;
    const int chunk   = lane >> 1;           // 0..15
    const int b       = warp_id * 2 + bsub;

    // per-k parameter prefix products (uniform)
    float AFh[4], AIh[4], AG[4], AOh[4];
    {
        float pf_ = 1.0f, pi_ = 1.0f, pg_ = 1.0f, po_ = 1.0f;
#pragma unroll
        for (int j = 0; j < 4; ++j) {
            pf_ *= __cosf(prm_f[j]);
            pi_ *= __cosf(prm_i[j]);
            pg_ *= __cosf(prm_g[j]);
            po_ *= __cosf(prm_o[j]);
            AFh[j] = 0.5f * pf_;   // sigmoid poly takes arg/2
            AIh[j] = 0.5f * pi_;
            AG[j]  = pg_;
            AOh[j] = 0.5f * po_;
        }
    }

    const float4* __restrict__ xin = (const float4*)inp;
    const int t0 = chunk * CHUNK;

    // ---- pass 1: chunk aggregates; cache f and i*g ----
    float Fc[CHUNK][4];   // forget gates
    float Gc[CHUNK][4];   // i*g products
    float cl0 = 0.f, cl1 = 0.f, cl2 = 0.f, cl3 = 0.f;
    float pf0 = 1.f, pf1 = 1.f, pf2 = 1.f, pf3 = 1.f;

#pragma unroll
    for (int it = 0; it < CHUNK; ++it) {
        float4 x = xin[(t0 + it) * BATCH + b];
        float P0 = __cosf(x.x);
        float P1 = P0 * __cosf(x.y);
        float P2 = P1 * __cosf(x.z);
        float P3 = P2 * __cosf(x.w);

        float f, i, g, ig;
        f = sig_poly(AFh[0] * P0); i = sig_poly(AIh[0] * P0); g = tanh_p54(AG[0] * P0);
        ig = i * g; Fc[it][0] = f; Gc[it][0] = ig;
        cl0 = fmaf(f, cl0, ig); pf0 *= f;

        f = sig_poly(AFh[1] * P1); i = sig_poly(AIh[1] * P1); g = tanh_p54(AG[1] * P1);
        ig = i * g; Fc[it][1] = f; Gc[it][1] = ig;
        cl1 = fmaf(f, cl1, ig); pf1 *= f;

        f = sig_poly(AFh[2] * P2); i = sig_poly(AIh[2] * P2); g = tanh_p54(AG[2] * P2);
        ig = i * g; Fc[it][2] = f; Gc[it][2] = ig;
        cl2 = fmaf(f, cl2, ig); pf2 *= f;

        f = sig_poly(AFh[3] * P3); i = sig_poly(AIh[3] * P3); g = tanh_p54(AG[3] * P3);
        ig = i * g; Fc[it][3] = f; Gc[it][3] = ig;
        cl3 = fmaf(f, cl3, ig); pf3 *= f;
    }

    // ---- scan over 16 chunks (same bsub = lanes stride 2) ----
    float F0 = pf0, C0 = cl0, F1 = pf1, C1 = cl1;
    float F2 = pf2, C2 = cl2, F3 = pf3, C3 = cl3;
#pragma unroll
    for (int off = 1; off <= 8; off <<= 1) {
        const int ol = off * 2;   // offset in lanes
        float Fo0 = __shfl_up_sync(FULLMASK, F0, ol), Co0 = __shfl_up_sync(FULLMASK, C0, ol);
        float Fo1 = __shfl_up_sync(FULLMASK, F1, ol), Co1 = __shfl_up_sync(FULLMASK, C1, ol);
        float Fo2 = __shfl_up_sync(FULLMASK, F2, ol), Co2 = __shfl_up_sync(FULLMASK, C2, ol);
        float Fo3 = __shfl_up_sync(FULLMASK, F3, ol), Co3 = __shfl_up_sync(FULLMASK, C3, ol);
        if (chunk >= off) {
            C0 = fmaf(F0, Co0, C0); F0 *= Fo0;
            C1 = fmaf(F1, Co1, C1); F1 *= Fo1;
            C2 = fmaf(F2, Co2, C2); F2 *= Fo2;
            C3 = fmaf(F3, Co3, C3); F3 *= Fo3;
        }
    }
    float c0 = __shfl_up_sync(FULLMASK, C0, 2);
    float c1 = __shfl_up_sync(FULLMASK, C1, 2);
    float c2 = __shfl_up_sync(FULLMASK, C2, 2);
    float c3 = __shfl_up_sync(FULLMASK, C3, 2);
    if (chunk == 0) { c0 = 0.f; c1 = 0.f; c2 = 0.f; c3 = 0.f; }

    // ---- pass 2: exact recurrence; reload x only for o-gate ----
    float4* __restrict__ out4 = (float4*)out;
    float h0 = 0.f, h1 = 0.f, h2 = 0.f, h3 = 0.f;

#pragma unroll
    for (int it = 0; it < CHUNK; ++it) {
        float4 x = xin[(t0 + it) * BATCH + b];
        float P0 = __cosf(x.x);
        float P1 = P0 * __cosf(x.y);
        float P2 = P1 * __cosf(x.z);
        float P3 = P2 * __cosf(x.w);

        c0 = fmaf(Fc[it][0], c0, Gc[it][0]);
        c1 = fmaf(Fc[it][1], c1, Gc[it][1]);
        c2 = fmaf(Fc[it][2], c2, Gc[it][2]);
        c3 = fmaf(Fc[it][3], c3, Gc[it][3]);

        h0 = sig_poly(AOh[0] * P0) * tanh_p76(c0);
        h1 = sig_poly(AOh[1] * P1) * tanh_p76(c1);
        h2 = sig_poly(AOh[2] * P2) * tanh_p76(c2);
        h3 = sig_poly(AOh[3] * P3) * tanh_p76(c3);

        out4[(t0 + it) * BATCH + b] = make_float4(h0, h1, h2, h3);
    }

    if (chunk == NCHUNK - 1) {
        out4[T_STEPS * BATCH + b]         = make_float4(h0, h1, h2, h3); // hx
        out4[T_STEPS * BATCH + BATCH + b] = make_float4(c0, c1, c2, c3); // cx
    }
}

extern "C" void kernel_launch(void* const* d_in, const int* in_sizes, int n_in,
                              void* d_out, int out_size) {
    (void)in_sizes; (void)n_in; (void)out_size;
    const float* inp   = (const float*)d_in[0];
    const float* prm_f = (const float*)d_in[1];
    const float* prm_i = (const float*)d_in[2];
    const float* prm_g = (const float*)d_in[3];
    const float* prm_o = (const float*)d_in[4];
    float* out = (float*)d_out;

    // 2048 warps (2 batch per warp), 4 warps per block -> 512 blocks
    qlstm_kernel<<<512, 128>>>(inp, prm_f, prm_i, prm_g, prm_o, out);
}